// round 1
// baseline (speedup 1.0000x reference)
#include <cuda_runtime.h>
#include <math.h>

// ---------------- problem constants ----------------
#define BATCH   8
#define NNODE   2048
#define MTOT    (BATCH*NNODE)   // 16384
#define HID     256
#define ATN     64
#define EMB     255             // IN_FEAT-1
#define QKV     384             // 64 q + 64 k + 256 v
#define KDIM    256
#define CAP     512             // max neighbors stored per node (mean ~20)

// ---------------- scratch (__device__ globals; no allocations allowed) ----------
__device__ float g_feats[MTOT*HID];
__device__ float g_h0[MTOT*HID];
__device__ float g_h1[MTOT*HID];
__device__ float g_qkv[MTOT*QKV];
__device__ float g_Wqkv[HID*QKV];
__device__ int   g_nbr[(size_t)MTOT*CAP];
__device__ int   g_cnt[MTOT];

// ---------------- build concatenated QKV weights ----------------
__global__ void concat_w_kernel(const float* __restrict__ Wq,
                                const float* __restrict__ Wk,
                                const float* __restrict__ Wv) {
    int idx = blockIdx.x * blockDim.x + threadIdx.x;
    if (idx >= HID*QKV) return;
    int k = idx / QKV, c = idx % QKV;
    float v;
    if (c < 64)        v = Wq[k*64 + c];
    else if (c < 128)  v = Wk[k*64 + (c-64)];
    else               v = Wv[k*256 + (c-128)];
    g_Wqkv[idx] = v;
}

// ---------------- features: embedding gather + cue ----------------
__global__ void feats_kernel(const int* __restrict__ x,
                             const int* __restrict__ cue,
                             const float* __restrict__ emb) {
    int m = blockIdx.x;
    int t = threadIdx.x;
    float v;
    if (t < EMB) {
        int xi = x[m];
        v = emb[(size_t)xi * EMB + t];
    } else {
        v = (float)cue[m];
    }
    g_feats[(size_t)m*HID + t] = v;
}

// ---------------- adjacency -> neighbor lists (deterministic, ordered) --------
__global__ void build_nbr_kernel(const float* __restrict__ adj) {
    int row  = blockIdx.x * (blockDim.x >> 5) + (threadIdx.x >> 5);
    int lane = threadIdx.x & 31;
    const float* ar = adj + (size_t)row * NNODE;
    int* dst = g_nbr + (size_t)row * CAP;
    int base = 0;
    for (int j0 = 0; j0 < NNODE; j0 += 32) {
        int j = j0 + lane;
        bool hit = ar[j] > 0.0f;
        unsigned msk = __ballot_sync(0xffffffffu, hit);
        if (hit) {
            int pos = base + __popc(msk & ((1u << lane) - 1u));
            if (pos < CAP) dst[pos] = j;
        }
        base += __popc(msk);
    }
    if (lane == 0) g_cnt[row] = min(base, CAP);
}

// ---------------- fp32 tiled SGEMM: C[M,N] = A[M,256] * B[256,N] --------------
// BM=128, BN=64, BK=32, TM=8, TN=4, 256 threads. M, N multiples of tile sizes.
template<bool RELU_BIAS>
__global__ void __launch_bounds__(256)
sgemm_kernel(const float* __restrict__ A, const float* __restrict__ Bm,
             float* __restrict__ C, int N, const float* __restrict__ bias) {
    constexpr int BM = 128, BN = 64, BK = 32, TM = 8, TN = 4;
    __shared__ __align__(16) float As[BK*BM];
    __shared__ __align__(16) float Bs[BK*BN];

    int tid = threadIdx.x;
    int bx = blockIdx.x, by = blockIdx.y;

    int arow = tid >> 3;            // 0..31
    int acol = (tid & 7) * 4;       // 0..28
    int brow = tid >> 4;            // 0..15
    int bcol = (tid & 15) * 4;      // 0..60

    const float* Ab = A + (size_t)(by * BM) * KDIM;
    const float* Bb = Bm + bx * BN;

    int ty = tid >> 4, tx = tid & 15;
    int m0 = ty * TM, n0 = tx * TN;

    float acc[TM][TN];
    #pragma unroll
    for (int i = 0; i < TM; i++)
        #pragma unroll
        for (int j = 0; j < TN; j++) acc[i][j] = 0.0f;

    for (int kt = 0; kt < KDIM; kt += BK) {
        #pragma unroll
        for (int i = 0; i < 4; i++) {
            int r = arow + i * 32;
            float4 v = *reinterpret_cast<const float4*>(Ab + (size_t)r*KDIM + kt + acol);
            As[(acol+0)*BM + r] = v.x;
            As[(acol+1)*BM + r] = v.y;
            As[(acol+2)*BM + r] = v.z;
            As[(acol+3)*BM + r] = v.w;
        }
        #pragma unroll
        for (int i = 0; i < 2; i++) {
            int r = brow + i * 16;
            *reinterpret_cast<float4*>(&Bs[r*BN + bcol]) =
                *reinterpret_cast<const float4*>(Bb + (size_t)(kt + r)*N + bcol);
        }
        __syncthreads();

        #pragma unroll
        for (int k = 0; k < BK; k++) {
            float4 a0 = *reinterpret_cast<const float4*>(&As[k*BM + m0]);
            float4 a1 = *reinterpret_cast<const float4*>(&As[k*BM + m0 + 4]);
            float4 bv = *reinterpret_cast<const float4*>(&Bs[k*BN + n0]);
            float a[TM] = {a0.x,a0.y,a0.z,a0.w,a1.x,a1.y,a1.z,a1.w};
            float b[TN] = {bv.x,bv.y,bv.z,bv.w};
            #pragma unroll
            for (int i = 0; i < TM; i++)
                #pragma unroll
                for (int j = 0; j < TN; j++)
                    acc[i][j] = fmaf(a[i], b[j], acc[i][j]);
        }
        __syncthreads();
    }

    float bb[TN] = {0,0,0,0};
    if (RELU_BIAS) {
        float4 bv = *reinterpret_cast<const float4*>(&bias[bx*BN + n0]);
        bb[0]=bv.x; bb[1]=bv.y; bb[2]=bv.z; bb[3]=bv.w;
    }
    #pragma unroll
    for (int i = 0; i < TM; i++) {
        float4 o;
        float v0 = acc[i][0], v1 = acc[i][1], v2 = acc[i][2], v3 = acc[i][3];
        if (RELU_BIAS) {
            v0 = fmaxf(v0 + bb[0], 0.0f);
            v1 = fmaxf(v1 + bb[1], 0.0f);
            v2 = fmaxf(v2 + bb[2], 0.0f);
            v3 = fmaxf(v3 + bb[3], 0.0f);
        }
        o.x=v0; o.y=v1; o.z=v2; o.w=v3;
        *reinterpret_cast<float4*>(&C[(size_t)(by*BM + m0 + i)*N + bx*BN + n0]) = o;
    }
}

// ---------------- sparse graph attention (one block of 256 per node) ----------
__global__ void __launch_bounds__(256)
attn_kernel(const float* __restrict__ qkv, float* __restrict__ hout,
            const float* __restrict__ gcb) {
    int node = blockIdx.x;
    int t = threadIdx.x;
    __shared__ float q_sh[ATN];
    __shared__ float p_sh[CAP];
    __shared__ float s_inv;

    int cnt = g_cnt[node];
    if (cnt == 0) {
        float g = gcb[t];
        hout[(size_t)node*HID + t] = 1.0f / (1.0f + __expf(-g));
        return;
    }
    if (t < ATN) q_sh[t] = qkv[(size_t)node*QKV + t];
    __syncthreads();

    int wid = t >> 5, lane = t & 31;
    const int* nl = g_nbr + (size_t)node * CAP;

    // logits: one warp per neighbor, strided
    for (int jn = wid; jn < cnt; jn += 8) {
        int j = nl[jn];
        const float* krow = qkv + (size_t)j*QKV + ATN;
        float d = q_sh[lane]*krow[lane] + q_sh[lane+32]*krow[lane+32];
        #pragma unroll
        for (int o = 16; o; o >>= 1) d += __shfl_xor_sync(0xffffffffu, d, o);
        if (lane == 0) p_sh[jn] = d;
    }
    __syncthreads();

    // softmax over neighbors (warp 0)
    if (wid == 0) {
        float mx = -1e30f;
        for (int jn = lane; jn < cnt; jn += 32) mx = fmaxf(mx, p_sh[jn]);
        #pragma unroll
        for (int o = 16; o; o >>= 1) mx = fmaxf(mx, __shfl_xor_sync(0xffffffffu, mx, o));
        float sum = 0.0f;
        for (int jn = lane; jn < cnt; jn += 32) {
            float e = __expf(p_sh[jn] - mx);
            p_sh[jn] = e;
            sum += e;
        }
        #pragma unroll
        for (int o = 16; o; o >>= 1) sum += __shfl_xor_sync(0xffffffffu, sum, o);
        if (lane == 0) s_inv = 1.0f / sum;
    }
    __syncthreads();

    // weighted sum of v rows; thread t owns output dim t
    float inv = s_inv;
    float acc = 0.0f;
    for (int jn = 0; jn < cnt; jn++) {
        int j = nl[jn];
        acc = fmaf(p_sh[jn], qkv[(size_t)j*QKV + 128 + t], acc);
    }
    float val = acc * inv + gcb[t];
    hout[(size_t)node*HID + t] = 1.0f / (1.0f + __expf(-val));
}

// ---------------- classifier + softmax (warp per node) ----------------
__global__ void __launch_bounds__(256)
classify_kernel(const float* __restrict__ h, const float* __restrict__ Wc,
                const float* __restrict__ bc, float* __restrict__ out) {
    int node = blockIdx.x * 8 + (threadIdx.x >> 5);
    int lane = threadIdx.x & 31;
    const float* hr = h + (size_t)node * HID;
    float a0 = 0.0f, a1 = 0.0f;
    #pragma unroll
    for (int d = lane; d < HID; d += 32) {
        float hv = hr[d];
        a0 = fmaf(hv, Wc[d*2+0], a0);
        a1 = fmaf(hv, Wc[d*2+1], a1);
    }
    #pragma unroll
    for (int o = 16; o; o >>= 1) {
        a0 += __shfl_xor_sync(0xffffffffu, a0, o);
        a1 += __shfl_xor_sync(0xffffffffu, a1, o);
    }
    if (lane == 0) {
        a0 += bc[0]; a1 += bc[1];
        float m = fmaxf(a0, a1);
        float e0 = __expf(a0 - m), e1 = __expf(a1 - m);
        float inv = 1.0f / (e0 + e1);
        out[node*2 + 0] = e0 * inv;
        out[node*2 + 1] = e1 * inv;
    }
}

// ---------------- launch ----------------
extern "C" void kernel_launch(void* const* d_in, const int* in_sizes, int n_in,
                              void* d_out, int out_size) {
    const int*   x   = (const int*)  d_in[0];
    const int*   cue = (const int*)  d_in[1];
    const float* adj = (const float*)d_in[2];
    const float* emb = (const float*)d_in[3];
    const float* Wh  = (const float*)d_in[4];
    const float* bh  = (const float*)d_in[5];
    const float* Wq  = (const float*)d_in[6];
    const float* Wk  = (const float*)d_in[7];
    const float* Wv  = (const float*)d_in[8];
    const float* gcb = (const float*)d_in[9];
    const float* Wc  = (const float*)d_in[10];
    const float* bc  = (const float*)d_in[11];
    float* out = (float*)d_out;

    void *p_feats, *p_h0, *p_h1, *p_qkv, *p_Wqkv;
    cudaGetSymbolAddress(&p_feats, g_feats);
    cudaGetSymbolAddress(&p_h0,    g_h0);
    cudaGetSymbolAddress(&p_h1,    g_h1);
    cudaGetSymbolAddress(&p_qkv,   g_qkv);
    cudaGetSymbolAddress(&p_Wqkv,  g_Wqkv);
    float* feats = (float*)p_feats;
    float* h0    = (float*)p_h0;
    float* h1    = (float*)p_h1;
    float* qkv   = (float*)p_qkv;
    float* Wqkv  = (float*)p_Wqkv;

    // independent prep
    concat_w_kernel<<<(HID*QKV + 255)/256, 256>>>(Wq, Wk, Wv);
    feats_kernel<<<MTOT, 256>>>(x, cue, emb);
    build_nbr_kernel<<<MTOT/8, 256>>>(adj);

    // h0 = relu(feats @ Wh + bh)
    {
        dim3 grid(HID/64, MTOT/128);
        sgemm_kernel<true><<<grid, 256>>>(feats, Wh, h0, HID, bh);
    }

    // two attention layers
    float* hin = h0;
    float* hot = h1;
    for (int L = 0; L < 2; L++) {
        dim3 grid(QKV/64, MTOT/128);
        sgemm_kernel<false><<<grid, 256>>>(hin, Wqkv, qkv, QKV, nullptr);
        attn_kernel<<<MTOT, 256>>>(qkv, hot, gcb);
        float* tmp = hin; hin = hot; hot = tmp;
    }

    // classifier + 2-class softmax
    classify_kernel<<<MTOT/8, 256>>>(hin, Wc, bc, out);
}

// round 3
// speedup vs baseline: 1.6187x; 1.6187x over previous
#include <cuda_runtime.h>
#include <cstdint>
#include <math.h>

// ---------------- problem constants ----------------
#define BATCH   8
#define NNODE   2048
#define MTOT    16384
#define HID     256
#define ATN     64
#define EMB     255
#define QKV     384
#define KDIM    256
#define CAP     512

// ---------------- device scratch ----------------
__device__ float g_feats[MTOT*HID];
__device__ float g_h0[MTOT*HID];
__device__ float g_h1[MTOT*HID];
__device__ float g_qkv[(size_t)MTOT*QKV];
__device__ float g_WhT[HID*KDIM];     // [N=256 rows][K=256]
__device__ float g_WqkvT[QKV*KDIM];   // [N=384 rows][K=256]
__device__ int   g_nbr[(size_t)MTOT*CAP];
__device__ int   g_cnt[MTOT];

__device__ __forceinline__ float tf32r(float x) {
    float y; asm("cvt.rna.tf32.f32 %0, %1;" : "=f"(y) : "f"(x)); return y;
}

// ---------------- weight prep: transpose (+ tf32 round) ----------------
__global__ void prep_w_kernel(const float* __restrict__ Wh, const float* __restrict__ Wq,
                              const float* __restrict__ Wk, const float* __restrict__ Wv) {
    int idx = blockIdx.x * 256 + threadIdx.x;     // 0 .. 384*256-1
    int n = idx >> 8, k = idx & 255;
    if (idx < 256*256)
        g_WhT[n*256 + k] = tf32r(Wh[k*256 + n]);
    float v = (n < 64) ? Wq[k*64 + n] : (n < 128) ? Wk[k*64 + (n-64)] : Wv[k*256 + (n-128)];
    g_WqkvT[n*256 + k] = tf32r(v);
}

// ---------------- features ----------------
__global__ void feats_kernel(const int* __restrict__ x, const int* __restrict__ cue,
                             const float* __restrict__ emb) {
    int m = blockIdx.x, t = threadIdx.x;
    float v;
    if (t < EMB) v = emb[(size_t)x[m] * EMB + t];
    else         v = (float)cue[m];
    g_feats[(size_t)m*HID + t] = v;
}

// ---------------- adjacency -> neighbor lists (float4 + warp scan) ----------------
__global__ void build_nbr_kernel(const float* __restrict__ adj) {
    int row  = blockIdx.x * 8 + (threadIdx.x >> 5);
    int lane = threadIdx.x & 31;
    const float4* ar = reinterpret_cast<const float4*>(adj + (size_t)row * NNODE);
    int* dst = g_nbr + (size_t)row * CAP;
    int base = 0;
    for (int j0 = 0; j0 < NNODE; j0 += 128) {
        float4 v = ar[(j0 >> 2) + lane];
        int h0 = v.x > 0.f, h1 = v.y > 0.f, h2 = v.z > 0.f, h3 = v.w > 0.f;
        int c4 = h0 + h1 + h2 + h3;
        int sc = c4;
        #pragma unroll
        for (int o = 1; o < 32; o <<= 1) {
            int nx = __shfl_up_sync(0xffffffffu, sc, o);
            if (lane >= o) sc += nx;
        }
        int pos = base + sc - c4;
        int jb = j0 + lane*4;
        if (h0) { if (pos < CAP) dst[pos] = jb;   pos++; }
        if (h1) { if (pos < CAP) dst[pos] = jb+1; pos++; }
        if (h2) { if (pos < CAP) dst[pos] = jb+2; pos++; }
        if (h3) { if (pos < CAP) dst[pos] = jb+3; pos++; }
        base += __shfl_sync(0xffffffffu, sc, 31);
    }
    if (lane == 0) g_cnt[row] = min(base, CAP);
}

// ---------------- tf32 mma.sync GEMM: C[M,N] = A[M,256] @ BT[N,256]^T --------
// CTA: 256 threads, tile 128(M) x 64(N), BK=32. Warp grid 4x2, warp tile 32x32.
// Fragments per warp: 2 m16-frags x 4 n8-frags, K inner loop of 4 x k8.
#define APAD 36

__device__ __forceinline__ void mma_tf32(float* c, const uint32_t* a, const uint32_t* b) {
    asm volatile(
        "mma.sync.aligned.m16n8k8.row.col.f32.tf32.tf32.f32 "
        "{%0,%1,%2,%3}, {%4,%5,%6,%7}, {%8,%9}, {%0,%1,%2,%3};"
        : "+f"(c[0]), "+f"(c[1]), "+f"(c[2]), "+f"(c[3])
        : "r"(a[0]), "r"(a[1]), "r"(a[2]), "r"(a[3]), "r"(b[0]), "r"(b[1]));
}

template<bool RB>
__global__ void __launch_bounds__(256, 2)
gemm_mma_kernel(const float* __restrict__ A, const float* __restrict__ BT,
                float* __restrict__ C, int N, const float* __restrict__ bias) {
    __shared__ float As[128*APAD];
    __shared__ float Bs[64*APAD];

    const int tid = threadIdx.x;
    const int lane = tid & 31, wid = tid >> 5;
    const int wm = (wid & 3) * 32;      // warp m offset within CTA tile
    const int wn = (wid >> 2) * 32;     // warp n offset
    const int m0 = blockIdx.y * 128;
    const int n0 = blockIdx.x * 64;
    const int r   = lane >> 2;          // 0..7
    const int cql = lane & 3;           // 0..3

    float acc[2][4][4];
    #pragma unroll
    for (int i = 0; i < 2; i++)
        #pragma unroll
        for (int j = 0; j < 4; j++)
            #pragma unroll
            for (int e = 0; e < 4; e++) acc[i][j][e] = 0.0f;

    for (int kt = 0; kt < KDIM; kt += 32) {
        __syncthreads();
        // stage A tile 128x32
        #pragma unroll
        for (int i = 0; i < 4; i++) {
            int idx = tid + i*256;           // 0..1023
            int row = idx >> 3, c4 = (idx & 7) << 2;
            float4 v = *reinterpret_cast<const float4*>(A + (size_t)(m0+row)*KDIM + kt + c4);
            v.x = tf32r(v.x); v.y = tf32r(v.y); v.z = tf32r(v.z); v.w = tf32r(v.w);
            float* d = &As[row*APAD + c4];
            d[0]=v.x; d[1]=v.y; d[2]=v.z; d[3]=v.w;
        }
        // stage B tile 64x32 (BT already tf32-rounded except for activations path; round anyway is idempotent)
        #pragma unroll
        for (int i = 0; i < 2; i++) {
            int idx = tid + i*256;           // 0..511
            int row = idx >> 3, c4 = (idx & 7) << 2;
            float4 v = *reinterpret_cast<const float4*>(BT + (size_t)(n0+row)*KDIM + kt + c4);
            float* d = &Bs[row*APAD + c4];
            d[0]=v.x; d[1]=v.y; d[2]=v.z; d[3]=v.w;
        }
        __syncthreads();

        #pragma unroll
        for (int k8 = 0; k8 < 4; k8++) {
            const int kk = k8 * 8;
            uint32_t a[2][4], b[4][2];
            #pragma unroll
            for (int i = 0; i < 2; i++) {
                int rb = wm + i*16 + r;
                a[i][0] = __float_as_uint(As[rb*APAD + kk + cql]);
                a[i][1] = __float_as_uint(As[(rb+8)*APAD + kk + cql]);
                a[i][2] = __float_as_uint(As[rb*APAD + kk + cql + 4]);
                a[i][3] = __float_as_uint(As[(rb+8)*APAD + kk + cql + 4]);
            }
            #pragma unroll
            for (int j = 0; j < 4; j++) {
                int nb = wn + j*8 + r;
                b[j][0] = __float_as_uint(Bs[nb*APAD + kk + cql]);
                b[j][1] = __float_as_uint(Bs[nb*APAD + kk + cql + 4]);
            }
            #pragma unroll
            for (int i = 0; i < 2; i++)
                #pragma unroll
                for (int j = 0; j < 4; j++)
                    mma_tf32(acc[i][j], a[i], b[j]);
        }
    }

    // epilogue: fragments -> GMEM (float2 stores), optional bias+relu
    #pragma unroll
    for (int i = 0; i < 2; i++) {
        int row = m0 + wm + i*16 + r;
        #pragma unroll
        for (int j = 0; j < 4; j++) {
            int col = n0 + wn + j*8 + cql*2;
            float v0 = acc[i][j][0], v1 = acc[i][j][1];
            float v2 = acc[i][j][2], v3 = acc[i][j][3];
            if (RB) {
                float b0 = bias[col], b1 = bias[col+1];
                v0 = fmaxf(v0 + b0, 0.f); v1 = fmaxf(v1 + b1, 0.f);
                v2 = fmaxf(v2 + b0, 0.f); v3 = fmaxf(v3 + b1, 0.f);
            }
            *reinterpret_cast<float2*>(&C[(size_t)row*N + col])     = make_float2(v0, v1);
            *reinterpret_cast<float2*>(&C[(size_t)(row+8)*N + col]) = make_float2(v2, v3);
        }
    }
}

// ---------------- sparse graph attention ----------------
__global__ void __launch_bounds__(256)
attn_kernel(const float* __restrict__ qkv, float* __restrict__ hout,
            const float* __restrict__ gcb) {
    int node = blockIdx.x;
    int t = threadIdx.x;
    __shared__ float q_sh[ATN];
    __shared__ float p_sh[CAP];
    __shared__ float s_inv;
    __shared__ float part[8][HID];

    int cnt = g_cnt[node];
    if (cnt == 0) {
        float g = gcb[t];
        hout[(size_t)node*HID + t] = 1.0f / (1.0f + __expf(-g));
        return;
    }
    if (t < ATN) q_sh[t] = qkv[(size_t)node*QKV + t];
    __syncthreads();

    int wid = t >> 5, lane = t & 31;
    const int* nl = g_nbr + (size_t)node * CAP;

    for (int jn = wid; jn < cnt; jn += 8) {
        int j = nl[jn];
        const float* krow = qkv + (size_t)j*QKV + ATN;
        float d = q_sh[lane]*krow[lane] + q_sh[lane+32]*krow[lane+32];
        #pragma unroll
        for (int o = 16; o; o >>= 1) d += __shfl_xor_sync(0xffffffffu, d, o);
        if (lane == 0) p_sh[jn] = d;
    }
    __syncthreads();

    if (wid == 0) {
        float mx = -1e30f;
        for (int jn = lane; jn < cnt; jn += 32) mx = fmaxf(mx, p_sh[jn]);
        #pragma unroll
        for (int o = 16; o; o >>= 1) mx = fmaxf(mx, __shfl_xor_sync(0xffffffffu, mx, o));
        float sum = 0.0f;
        for (int jn = lane; jn < cnt; jn += 32) {
            float e = __expf(p_sh[jn] - mx);
            p_sh[jn] = e;
            sum += e;
        }
        #pragma unroll
        for (int o = 16; o; o >>= 1) sum += __shfl_xor_sync(0xffffffffu, sum, o);
        if (lane == 0) s_inv = 1.0f / sum;
    }
    __syncthreads();

    float acc[8] = {0,0,0,0,0,0,0,0};
    for (int jn = wid; jn < cnt; jn += 8) {
        int j = nl[jn];
        float p = p_sh[jn];
        const float* vr = qkv + (size_t)j*QKV + 128;
        #pragma unroll
        for (int ch = 0; ch < 8; ch++) acc[ch] = fmaf(p, vr[ch*32 + lane], acc[ch]);
    }
    #pragma unroll
    for (int ch = 0; ch < 8; ch++) part[wid][ch*32 + lane] = acc[ch];
    __syncthreads();

    float s = 0.0f;
    #pragma unroll
    for (int w2 = 0; w2 < 8; w2++) s += part[w2][t];
    float val = s * s_inv + gcb[t];
    hout[(size_t)node*HID + t] = 1.0f / (1.0f + __expf(-val));
}

// ---------------- classifier + softmax ----------------
__global__ void __launch_bounds__(256)
classify_kernel(const float* __restrict__ h, const float* __restrict__ Wc,
                const float* __restrict__ bc, float* __restrict__ out) {
    int node = blockIdx.x * 8 + (threadIdx.x >> 5);
    int lane = threadIdx.x & 31;
    const float* hr = h + (size_t)node * HID;
    float a0 = 0.0f, a1 = 0.0f;
    #pragma unroll
    for (int d = lane; d < HID; d += 32) {
        float hv = hr[d];
        a0 = fmaf(hv, Wc[d*2+0], a0);
        a1 = fmaf(hv, Wc[d*2+1], a1);
    }
    #pragma unroll
    for (int o = 16; o; o >>= 1) {
        a0 += __shfl_xor_sync(0xffffffffu, a0, o);
        a1 += __shfl_xor_sync(0xffffffffu, a1, o);
    }
    if (lane == 0) {
        a0 += bc[0]; a1 += bc[1];
        float m = fmaxf(a0, a1);
        float e0 = __expf(a0 - m), e1 = __expf(a1 - m);
        float inv = 1.0f / (e0 + e1);
        out[node*2 + 0] = e0 * inv;
        out[node*2 + 1] = e1 * inv;
    }
}

// ---------------- launch ----------------
extern "C" void kernel_launch(void* const* d_in, const int* in_sizes, int n_in,
                              void* d_out, int out_size) {
    const int*   x   = (const int*)  d_in[0];
    const int*   cue = (const int*)  d_in[1];
    const float* adj = (const float*)d_in[2];
    const float* emb = (const float*)d_in[3];
    const float* Wh  = (const float*)d_in[4];
    const float* bh  = (const float*)d_in[5];
    const float* Wq  = (const float*)d_in[6];
    const float* Wk  = (const float*)d_in[7];
    const float* Wv  = (const float*)d_in[8];
    const float* gcb = (const float*)d_in[9];
    const float* Wc  = (const float*)d_in[10];
    const float* bc  = (const float*)d_in[11];
    float* out = (float*)d_out;

    void *p_feats, *p_h0, *p_h1, *p_qkv, *p_WhT, *p_WqkvT;
    cudaGetSymbolAddress(&p_feats, g_feats);
    cudaGetSymbolAddress(&p_h0,    g_h0);
    cudaGetSymbolAddress(&p_h1,    g_h1);
    cudaGetSymbolAddress(&p_qkv,   g_qkv);
    cudaGetSymbolAddress(&p_WhT,   g_WhT);
    cudaGetSymbolAddress(&p_WqkvT, g_WqkvT);
    float* feats = (float*)p_feats;
    float* h0    = (float*)p_h0;
    float* h1    = (float*)p_h1;
    float* qkv   = (float*)p_qkv;
    float* WhT   = (float*)p_WhT;
    float* WqkvT = (float*)p_WqkvT;

    prep_w_kernel<<<QKV, 256>>>(Wh, Wq, Wk, Wv);
    feats_kernel<<<MTOT, 256>>>(x, cue, emb);
    build_nbr_kernel<<<MTOT/8, 256>>>(adj);

    // h0 = relu(feats @ Wh + bh)
    gemm_mma_kernel<true><<<dim3(HID/64, MTOT/128), 256>>>(feats, WhT, h0, HID, bh);

    float* hin = h0;
    float* hot = h1;
    for (int L = 0; L < 2; L++) {
        gemm_mma_kernel<false><<<dim3(QKV/64, MTOT/128), 256>>>(hin, WqkvT, qkv, QKV, nullptr);
        attn_kernel<<<MTOT, 256>>>(qkv, hot, gcb);
        float* tmp = hin; hin = hot; hot = tmp;
    }

    classify_kernel<<<MTOT/8, 256>>>(hin, Wc, bc, out);
}

// round 4
// speedup vs baseline: 2.1705x; 1.3409x over previous
#include <cuda_runtime.h>
#include <cuda_fp16.h>
#include <cstdint>
#include <math.h>

// ---------------- problem constants ----------------
#define BATCH   8
#define NNODE   2048
#define MTOT    16384
#define HID     256
#define ATN     64
#define EMB     255
#define QKV     384
#define KDIM    256
#define CAP     512
#define APAD    36

// ---------------- device scratch ----------------
__device__ float g_feats[MTOT*HID];
__device__ float g_h0[MTOT*HID];
__device__ float g_h1[MTOT*HID];
__device__ __align__(16) float  g_q[MTOT*ATN];
__device__ __align__(16) __half g_kh[MTOT*ATN];
__device__ __align__(16) __half g_vh[(size_t)MTOT*HID];
__device__ float g_WhT[HID*KDIM];     // [N=256 rows][K=256]
__device__ float g_WqkvT[QKV*KDIM];   // [N=384 rows][K=256]
__device__ int   g_nbr[(size_t)MTOT*CAP];
__device__ int   g_cnt[MTOT];

__device__ __forceinline__ float tf32r(float x) {
    float y; asm("cvt.rna.tf32.f32 %0, %1;" : "=f"(y) : "f"(x)); return y;
}
__device__ __forceinline__ uint32_t smem_u32(const void* p) {
    uint32_t a;
    asm("{ .reg .u64 t; cvta.to.shared.u64 t, %1; cvt.u32.u64 %0, t; }" : "=r"(a) : "l"(p));
    return a;
}
__device__ __forceinline__ void cp16(uint32_t dst, const void* src) {
    asm volatile("cp.async.cg.shared.global [%0], [%1], 16;" :: "r"(dst), "l"(src) : "memory");
}

// ---------------- weight prep: transpose (+ tf32 round) ----------------
__global__ void prep_w_kernel(const float* __restrict__ Wh, const float* __restrict__ Wq,
                              const float* __restrict__ Wk, const float* __restrict__ Wv) {
    int idx = blockIdx.x * 256 + threadIdx.x;
    int n = idx >> 8, k = idx & 255;
    if (idx < 256*256)
        g_WhT[n*256 + k] = tf32r(Wh[k*256 + n]);
    float v = (n < 64) ? Wq[k*64 + n] : (n < 128) ? Wk[k*64 + (n-64)] : Wv[k*256 + (n-128)];
    g_WqkvT[n*256 + k] = tf32r(v);
}

// ---------------- features ----------------
__global__ void feats_kernel(const int* __restrict__ x, const int* __restrict__ cue,
                             const float* __restrict__ emb) {
    int m = blockIdx.x, t = threadIdx.x;
    float v;
    if (t < EMB) v = emb[(size_t)x[m] * EMB + t];
    else         v = (float)cue[m];
    g_feats[(size_t)m*HID + t] = v;
}

// ---------------- adjacency -> neighbor lists ----------------
__global__ void build_nbr_kernel(const float* __restrict__ adj) {
    int row  = blockIdx.x * 8 + (threadIdx.x >> 5);
    int lane = threadIdx.x & 31;
    const float4* ar = reinterpret_cast<const float4*>(adj + (size_t)row * NNODE);
    int* dst = g_nbr + (size_t)row * CAP;
    int base = 0;
    for (int j0 = 0; j0 < NNODE; j0 += 128) {
        float4 v = ar[(j0 >> 2) + lane];
        int h0 = v.x > 0.f, h1 = v.y > 0.f, h2 = v.z > 0.f, h3 = v.w > 0.f;
        int c4 = h0 + h1 + h2 + h3;
        int sc = c4;
        #pragma unroll
        for (int o = 1; o < 32; o <<= 1) {
            int nx = __shfl_up_sync(0xffffffffu, sc, o);
            if (lane >= o) sc += nx;
        }
        int pos = base + sc - c4;
        int jb = j0 + lane*4;
        if (h0) { if (pos < CAP) dst[pos] = jb;   pos++; }
        if (h1) { if (pos < CAP) dst[pos] = jb+1; pos++; }
        if (h2) { if (pos < CAP) dst[pos] = jb+2; pos++; }
        if (h3) { if (pos < CAP) dst[pos] = jb+3; pos++; }
        base += __shfl_sync(0xffffffffu, sc, 31);
    }
    if (lane == 0) g_cnt[row] = min(base, CAP);
}

// ---------------- tf32 mma.sync GEMM, cp.async 2-stage, tile 128x128xBK32 ----
// MODE 0: C = relu(A@BT^T + bias), N=256 fp32
// MODE 1: N=384; cols [0,64) -> qo fp32; [64,128) -> kho half; [128,384) -> vho half
__device__ __forceinline__ void mma_tf32(float* c, const uint32_t* a, const uint32_t* b) {
    asm volatile(
        "mma.sync.aligned.m16n8k8.row.col.f32.tf32.tf32.f32 "
        "{%0,%1,%2,%3}, {%4,%5,%6,%7}, {%8,%9}, {%0,%1,%2,%3};"
        : "+f"(c[0]), "+f"(c[1]), "+f"(c[2]), "+f"(c[3])
        : "r"(a[0]), "r"(a[1]), "r"(a[2]), "r"(a[3]), "r"(b[0]), "r"(b[1]));
}

#define BUF_FLOATS (128*APAD)        // 4608 per matrix
#define SMEM_FLOATS (4*BUF_FLOATS)   // 2 bufs x (A,B)
#define SMEM_BYTES  (SMEM_FLOATS*4)  // 73728

template<int MODE>
__global__ void __launch_bounds__(256, 2)
gemm2_kernel(const float* __restrict__ A, const float* __restrict__ BT,
             float* __restrict__ C, const float* __restrict__ bias,
             float* __restrict__ qo, __half* __restrict__ kho, __half* __restrict__ vho) {
    extern __shared__ float sm[];
    const int tid = threadIdx.x;
    const int lane = tid & 31, wid = tid >> 5;
    const int wm = (wid & 3) * 32;
    const int wn = (wid >> 2) * 64;
    const int m0 = blockIdx.y * 128;
    const int n0 = blockIdx.x * 128;
    const int r = lane >> 2, cql = lane & 3;
    const uint32_t sbase = smem_u32(sm);

    float acc[2][8][4];
    #pragma unroll
    for (int i = 0; i < 2; i++)
        #pragma unroll
        for (int j = 0; j < 8; j++)
            #pragma unroll
            for (int e = 0; e < 4; e++) acc[i][j][e] = 0.0f;

    // ---- stage chunk kt into buffer buf via cp.async ----
    auto stage = [&](int buf, int kt) {
        uint32_t dbase = sbase + (uint32_t)(buf * 2 * BUF_FLOATS) * 4u;
        #pragma unroll
        for (int i = 0; i < 4; i++) {
            int idx = tid + i*256;
            int row = idx >> 3, c4 = (idx & 7) << 2;
            cp16(dbase + (uint32_t)(row*APAD + c4)*4u,
                 A + (size_t)(m0+row)*KDIM + kt + c4);
        }
        #pragma unroll
        for (int i = 0; i < 4; i++) {
            int idx = tid + i*256;
            int row = idx >> 3, c4 = (idx & 7) << 2;
            cp16(dbase + (uint32_t)(BUF_FLOATS + row*APAD + c4)*4u,
                 BT + (size_t)(n0+row)*KDIM + kt + c4);
        }
        asm volatile("cp.async.commit_group;" ::: "memory");
    };

    stage(0, 0);
    for (int c = 0; c < 8; c++) {
        asm volatile("cp.async.wait_group 0;" ::: "memory");
        __syncthreads();
        if (c < 7) stage((c+1) & 1, (c+1)*32);

        const float* As = sm + (c & 1) * 2 * BUF_FLOATS;
        const float* Bs = As + BUF_FLOATS;

        #pragma unroll
        for (int k8 = 0; k8 < 4; k8++) {
            const int kk = k8 * 8;
            uint32_t a[2][4], b[8][2];
            #pragma unroll
            for (int i = 0; i < 2; i++) {
                int rb = wm + i*16 + r;
                a[i][0] = __float_as_uint(As[rb*APAD + kk + cql]);
                a[i][1] = __float_as_uint(As[(rb+8)*APAD + kk + cql]);
                a[i][2] = __float_as_uint(As[rb*APAD + kk + cql + 4]);
                a[i][3] = __float_as_uint(As[(rb+8)*APAD + kk + cql + 4]);
            }
            #pragma unroll
            for (int j = 0; j < 8; j++) {
                int nb = wn + j*8 + r;
                b[j][0] = __float_as_uint(Bs[nb*APAD + kk + cql]);
                b[j][1] = __float_as_uint(Bs[nb*APAD + kk + cql + 4]);
            }
            #pragma unroll
            for (int i = 0; i < 2; i++)
                #pragma unroll
                for (int j = 0; j < 8; j++)
                    mma_tf32(acc[i][j], a[i], b[j]);
        }
        __syncthreads();
    }

    // ---- epilogue ----
    #pragma unroll
    for (int i = 0; i < 2; i++) {
        int row = m0 + wm + i*16 + r;
        #pragma unroll
        for (int j = 0; j < 8; j++) {
            int col = n0 + wn + j*8 + cql*2;
            float v0 = acc[i][j][0], v1 = acc[i][j][1];
            float v2 = acc[i][j][2], v3 = acc[i][j][3];
            if (MODE == 0) {
                float b0 = bias[col], b1 = bias[col+1];
                v0 = fmaxf(v0 + b0, 0.f); v1 = fmaxf(v1 + b1, 0.f);
                v2 = fmaxf(v2 + b0, 0.f); v3 = fmaxf(v3 + b1, 0.f);
                *reinterpret_cast<float2*>(&C[(size_t)row*HID + col])     = make_float2(v0, v1);
                *reinterpret_cast<float2*>(&C[(size_t)(row+8)*HID + col]) = make_float2(v2, v3);
            } else {
                if (col < 64) {
                    *reinterpret_cast<float2*>(&qo[(size_t)row*ATN + col])     = make_float2(v0, v1);
                    *reinterpret_cast<float2*>(&qo[(size_t)(row+8)*ATN + col]) = make_float2(v2, v3);
                } else if (col < 128) {
                    kho[(size_t)row*ATN + (col-64)]     = __float2half(v0);
                    kho[(size_t)row*ATN + (col-64) + 1] = __float2half(v1);
                    kho[(size_t)(row+8)*ATN + (col-64)]     = __float2half(v2);
                    kho[(size_t)(row+8)*ATN + (col-64) + 1] = __float2half(v3);
                } else {
                    *reinterpret_cast<__half2*>(&vho[(size_t)row*HID + (col-128)]) = __floats2half2_rn(v0, v1);
                    *reinterpret_cast<__half2*>(&vho[(size_t)(row+8)*HID + (col-128)]) = __floats2half2_rn(v2, v3);
                }
            }
        }
    }
}

// ---------------- sparse graph attention: warp per node ----------------
__global__ void __launch_bounds__(256)
attn_kernel(const float* __restrict__ q, const __half* __restrict__ kh,
            const __half* __restrict__ vh, float* __restrict__ hout,
            const float* __restrict__ gcb) {
    const int wid = threadIdx.x >> 5, lane = threadIdx.x & 31;
    const int node = blockIdx.x * 8 + wid;
    __shared__ float qs[8][64];
    __shared__ float ps[8][CAP];

    const int cnt = g_cnt[node];
    if (cnt == 0) {
        #pragma unroll
        for (int e = 0; e < 8; e++) {
            float g = gcb[lane*8 + e];
            hout[(size_t)node*HID + lane*8 + e] = 1.0f / (1.0f + __expf(-g));
        }
        return;
    }

    // q row -> smem
    float2 qv = reinterpret_cast<const float2*>(q + (size_t)node*ATN)[lane];
    qs[wid][2*lane]   = qv.x;
    qs[wid][2*lane+1] = qv.y;
    __syncwarp();

    const int* nl = g_nbr + (size_t)node * CAP;

    // logits: neighbor-parallel (one neighbor per lane)
    for (int t0 = 0; t0 < cnt; t0 += 32) {
        int jn = t0 + lane;
        if (jn < cnt) {
            int j = nl[jn];
            const uint4* kp = reinterpret_cast<const uint4*>(kh + (size_t)j*ATN);
            float d = 0.0f;
            #pragma unroll
            for (int b = 0; b < 8; b++) {
                uint4 kk = kp[b];
                const __half2* hp = reinterpret_cast<const __half2*>(&kk);
                #pragma unroll
                for (int e = 0; e < 4; e++) {
                    float2 f = __half22float2(hp[e]);
                    d = fmaf(qs[wid][b*8 + 2*e],     f.x, d);
                    d = fmaf(qs[wid][b*8 + 2*e + 1], f.y, d);
                }
            }
            ps[wid][jn] = d;
        }
    }
    __syncwarp();

    // softmax over neighbors (in-warp)
    float mx = -1e30f;
    for (int jn = lane; jn < cnt; jn += 32) mx = fmaxf(mx, ps[wid][jn]);
    #pragma unroll
    for (int o = 16; o; o >>= 1) mx = fmaxf(mx, __shfl_xor_sync(0xffffffffu, mx, o));
    float sum = 0.0f;
    for (int jn = lane; jn < cnt; jn += 32) {
        float e = __expf(ps[wid][jn] - mx);
        ps[wid][jn] = e;
        sum += e;
    }
    #pragma unroll
    for (int o = 16; o; o >>= 1) sum += __shfl_xor_sync(0xffffffffu, sum, o);
    float sinv = 1.0f / sum;
    __syncwarp();

    // V accumulation: lane owns channels [lane*8, lane*8+8)
    float acc[8] = {0,0,0,0,0,0,0,0};
    for (int jn = 0; jn < cnt; jn++) {
        int j = nl[jn];
        float p = ps[wid][jn];
        uint4 vv = reinterpret_cast<const uint4*>(vh + (size_t)j*HID)[lane];
        const __half2* hp = reinterpret_cast<const __half2*>(&vv);
        #pragma unroll
        for (int e = 0; e < 4; e++) {
            float2 f = __half22float2(hp[e]);
            acc[2*e]   = fmaf(p, f.x, acc[2*e]);
            acc[2*e+1] = fmaf(p, f.y, acc[2*e+1]);
        }
    }

    float outv[8];
    #pragma unroll
    for (int e = 0; e < 8; e++) {
        float val = acc[e] * sinv + gcb[lane*8 + e];
        outv[e] = 1.0f / (1.0f + __expf(-val));
    }
    float4* op = reinterpret_cast<float4*>(hout + (size_t)node*HID + lane*8);
    op[0] = make_float4(outv[0], outv[1], outv[2], outv[3]);
    op[1] = make_float4(outv[4], outv[5], outv[6], outv[7]);
}

// ---------------- classifier + softmax ----------------
__global__ void __launch_bounds__(256)
classify_kernel(const float* __restrict__ h, const float* __restrict__ Wc,
                const float* __restrict__ bc, float* __restrict__ out) {
    int node = blockIdx.x * 8 + (threadIdx.x >> 5);
    int lane = threadIdx.x & 31;
    const float* hr = h + (size_t)node * HID;
    float a0 = 0.0f, a1 = 0.0f;
    #pragma unroll
    for (int d = lane; d < HID; d += 32) {
        float hv = hr[d];
        a0 = fmaf(hv, Wc[d*2+0], a0);
        a1 = fmaf(hv, Wc[d*2+1], a1);
    }
    #pragma unroll
    for (int o = 16; o; o >>= 1) {
        a0 += __shfl_xor_sync(0xffffffffu, a0, o);
        a1 += __shfl_xor_sync(0xffffffffu, a1, o);
    }
    if (lane == 0) {
        a0 += bc[0]; a1 += bc[1];
        float m = fmaxf(a0, a1);
        float e0 = __expf(a0 - m), e1 = __expf(a1 - m);
        float inv = 1.0f / (e0 + e1);
        out[node*2 + 0] = e0 * inv;
        out[node*2 + 1] = e1 * inv;
    }
}

// ---------------- launch ----------------
extern "C" void kernel_launch(void* const* d_in, const int* in_sizes, int n_in,
                              void* d_out, int out_size) {
    const int*   x   = (const int*)  d_in[0];
    const int*   cue = (const int*)  d_in[1];
    const float* adj = (const float*)d_in[2];
    const float* emb = (const float*)d_in[3];
    const float* Wh  = (const float*)d_in[4];
    const float* bh  = (const float*)d_in[5];
    const float* Wq  = (const float*)d_in[6];
    const float* Wk  = (const float*)d_in[7];
    const float* Wv  = (const float*)d_in[8];
    const float* gcb = (const float*)d_in[9];
    const float* Wc  = (const float*)d_in[10];
    const float* bc  = (const float*)d_in[11];
    float* out = (float*)d_out;

    void *p_feats, *p_h0, *p_h1, *p_q, *p_kh, *p_vh, *p_WhT, *p_WqkvT;
    cudaGetSymbolAddress(&p_feats, g_feats);
    cudaGetSymbolAddress(&p_h0,    g_h0);
    cudaGetSymbolAddress(&p_h1,    g_h1);
    cudaGetSymbolAddress(&p_q,     g_q);
    cudaGetSymbolAddress(&p_kh,    g_kh);
    cudaGetSymbolAddress(&p_vh,    g_vh);
    cudaGetSymbolAddress(&p_WhT,   g_WhT);
    cudaGetSymbolAddress(&p_WqkvT, g_WqkvT);
    float*  feats = (float*)p_feats;
    float*  h0    = (float*)p_h0;
    float*  h1    = (float*)p_h1;
    float*  qbuf  = (float*)p_q;
    __half* khb   = (__half*)p_kh;
    __half* vhb   = (__half*)p_vh;
    float*  WhT   = (float*)p_WhT;
    float*  WqkvT = (float*)p_WqkvT;

    cudaFuncSetAttribute(gemm2_kernel<0>, cudaFuncAttributeMaxDynamicSharedMemorySize, SMEM_BYTES);
    cudaFuncSetAttribute(gemm2_kernel<1>, cudaFuncAttributeMaxDynamicSharedMemorySize, SMEM_BYTES);

    prep_w_kernel<<<QKV, 256>>>(Wh, Wq, Wk, Wv);
    feats_kernel<<<MTOT, 256>>>(x, cue, emb);
    build_nbr_kernel<<<MTOT/8, 256>>>(adj);

    // h0 = relu(feats @ Wh + bh)
    gemm2_kernel<0><<<dim3(2, 128), 256, SMEM_BYTES>>>(feats, WhT, h0, bh, nullptr, nullptr, nullptr);

    float* hin = h0;
    float* hot = h1;
    for (int L = 0; L < 2; L++) {
        gemm2_kernel<1><<<dim3(3, 128), 256, SMEM_BYTES>>>(hin, WqkvT, nullptr, nullptr, qbuf, khb, vhb);
        attn_kernel<<<MTOT/8, 256>>>(qbuf, khb, vhb, hot, gcb);
        float* tmp = hin; hin = hot; hot = tmp;
    }

    classify_kernel<<<MTOT/8, 256>>>(hin, Wc, bc, out);
}

// round 5
// speedup vs baseline: 2.7019x; 1.2448x over previous
#include <cuda_runtime.h>
#include <cuda_fp16.h>
#include <cstdint>
#include <math.h>

// ---------------- problem constants ----------------
#define BATCH   8
#define NNODE   2048
#define MTOT    16384
#define HID     256
#define ATN     64
#define EMB     255
#define QKV     384
#define KDIM    256
#define CAP     512
#define HPAD    72            // padded row length in halves (conflict-free)

// ---------------- device scratch ----------------
__device__ __align__(16) __half g_feats[MTOT*HID];
__device__ __align__(16) __half g_h0[MTOT*HID];
__device__ __align__(16) __half g_h1[MTOT*HID];
__device__ __align__(16) __half g_q[MTOT*ATN];
__device__ __align__(16) __half g_kh[MTOT*ATN];
__device__ __align__(16) __half g_vh[(size_t)MTOT*HID];
__device__ __align__(16) __half g_WhT[HID*KDIM];     // [N=256][K=256]
__device__ __align__(16) __half g_WqkvT[QKV*KDIM];   // [N=384][K=256]
__device__ int   g_nbr[(size_t)MTOT*CAP];
__device__ int   g_cnt[MTOT];

__device__ __forceinline__ uint32_t smem_u32(const void* p) {
    uint32_t a;
    asm("{ .reg .u64 t; cvta.to.shared.u64 t, %1; cvt.u32.u64 %0, t; }" : "=r"(a) : "l"(p));
    return a;
}
__device__ __forceinline__ void cp16(uint32_t dst, const void* src) {
    asm volatile("cp.async.cg.shared.global [%0], [%1], 16;" :: "r"(dst), "l"(src) : "memory");
}

// ---------------- weight prep: transpose + half ----------------
__global__ void prep_w_kernel(const float* __restrict__ Wh, const float* __restrict__ Wq,
                              const float* __restrict__ Wk, const float* __restrict__ Wv) {
    int idx = blockIdx.x * 256 + threadIdx.x;      // 0 .. 384*256-1
    int n = idx >> 8, k = idx & 255;
    if (idx < 256*256)
        g_WhT[n*256 + k] = __float2half(Wh[k*256 + n]);
    float v = (n < 64) ? Wq[k*64 + n] : (n < 128) ? Wk[k*64 + (n-64)] : Wv[k*256 + (n-128)];
    g_WqkvT[n*256 + k] = __float2half(v);
}

// ---------------- features ----------------
__global__ void feats_kernel(const int* __restrict__ x, const int* __restrict__ cue,
                             const float* __restrict__ emb) {
    int m = blockIdx.x, t = threadIdx.x;
    float v;
    if (t < EMB) v = emb[(size_t)x[m] * EMB + t];
    else         v = (float)cue[m];
    g_feats[(size_t)m*HID + t] = __float2half(v);
}

// ---------------- adjacency -> neighbor lists ----------------
__global__ void build_nbr_kernel(const float* __restrict__ adj) {
    int row  = blockIdx.x * 8 + (threadIdx.x >> 5);
    int lane = threadIdx.x & 31;
    const float4* ar = reinterpret_cast<const float4*>(adj + (size_t)row * NNODE);
    int* dst = g_nbr + (size_t)row * CAP;
    int base = 0;
    for (int j0 = 0; j0 < NNODE; j0 += 128) {
        float4 v = ar[(j0 >> 2) + lane];
        int h0 = v.x > 0.f, h1 = v.y > 0.f, h2 = v.z > 0.f, h3 = v.w > 0.f;
        int c4 = h0 + h1 + h2 + h3;
        int sc = c4;
        #pragma unroll
        for (int o = 1; o < 32; o <<= 1) {
            int nx = __shfl_up_sync(0xffffffffu, sc, o);
            if (lane >= o) sc += nx;
        }
        int pos = base + sc - c4;
        int jb = j0 + lane*4;
        if (h0) { if (pos < CAP) dst[pos] = jb;   pos++; }
        if (h1) { if (pos < CAP) dst[pos] = jb+1; pos++; }
        if (h2) { if (pos < CAP) dst[pos] = jb+2; pos++; }
        if (h3) { if (pos < CAP) dst[pos] = jb+3; pos++; }
        base += __shfl_sync(0xffffffffu, sc, 31);
    }
    if (lane == 0) g_cnt[row] = min(base, CAP);
}

// ---------------- fp16 mma.sync GEMM, cp.async 2-stage, tile 128x128xBK64 ----
// MODE 0: C = relu(A@BT^T + bias) -> half, N=256
// MODE 1: N=384; cols [0,64)->q half; [64,128)->k half; [128,384)->v half
__device__ __forceinline__ void mma_f16(float* c, const uint32_t* a, const uint32_t* b) {
    asm volatile(
        "mma.sync.aligned.m16n8k16.row.col.f32.f16.f16.f32 "
        "{%0,%1,%2,%3}, {%4,%5,%6,%7}, {%8,%9}, {%0,%1,%2,%3};"
        : "+f"(c[0]), "+f"(c[1]), "+f"(c[2]), "+f"(c[3])
        : "r"(a[0]), "r"(a[1]), "r"(a[2]), "r"(a[3]), "r"(b[0]), "r"(b[1]));
}

#define TILE_HALVES (128*HPAD)                 // 9216 halves = 18432 B per matrix per stage
#define STAGE_HALVES (2*TILE_HALVES)           // A + B
#define SMEM_BYTES  (2*STAGE_HALVES*2)         // 2 stages = 73728 B

template<int MODE>
__global__ void __launch_bounds__(256, 2)
gemm_h_kernel(const __half* __restrict__ A, const __half* __restrict__ BT,
              __half* __restrict__ C, const float* __restrict__ bias,
              __half* __restrict__ qo, __half* __restrict__ kho, __half* __restrict__ vho) {
    extern __shared__ __half sm[];
    const int tid = threadIdx.x;
    const int lane = tid & 31, wid = tid >> 5;
    const int wm = (wid & 3) * 32;
    const int wn = (wid >> 2) * 64;
    const int m0 = blockIdx.y * 128;
    const int n0 = blockIdx.x * 128;
    const int r = lane >> 2, cql = lane & 3;
    const uint32_t sbase = smem_u32(sm);

    float acc[2][8][4];
    #pragma unroll
    for (int i = 0; i < 2; i++)
        #pragma unroll
        for (int j = 0; j < 8; j++)
            #pragma unroll
            for (int e = 0; e < 4; e++) acc[i][j][e] = 0.0f;

    // stage a BK=64 chunk (A 128x64 + B 128x64 halves) into buffer buf
    auto stage = [&](int buf, int kt) {
        uint32_t dbase = sbase + (uint32_t)(buf * STAGE_HALVES) * 2u;
        #pragma unroll
        for (int i = 0; i < 4; i++) {
            int idx = tid + i*256;               // 0..1023
            int row = idx >> 3, ck = (idx & 7) << 3;   // 8-half (16B) chunks
            cp16(dbase + (uint32_t)(row*HPAD + ck)*2u,
                 A + (size_t)(m0+row)*KDIM + kt + ck);
        }
        #pragma unroll
        for (int i = 0; i < 4; i++) {
            int idx = tid + i*256;
            int row = idx >> 3, ck = (idx & 7) << 3;
            cp16(dbase + (uint32_t)(TILE_HALVES + row*HPAD + ck)*2u,
                 BT + (size_t)(n0+row)*KDIM + kt + ck);
        }
        asm volatile("cp.async.commit_group;" ::: "memory");
    };

    stage(0, 0);
    for (int c = 0; c < 4; c++) {
        asm volatile("cp.async.wait_group 0;" ::: "memory");
        __syncthreads();
        if (c < 3) stage((c+1) & 1, (c+1)*64);

        const __half* As = sm + (c & 1) * STAGE_HALVES;
        const __half* Bs = As + TILE_HALVES;

        #pragma unroll
        for (int k16 = 0; k16 < 4; k16++) {
            const int kk = k16 * 16;
            uint32_t a[2][4], b[8][2];
            #pragma unroll
            for (int i = 0; i < 2; i++) {
                int rb = wm + i*16 + r;
                const __half* p0 = &As[rb*HPAD + kk + 2*cql];
                const __half* p1 = &As[(rb+8)*HPAD + kk + 2*cql];
                a[i][0] = *reinterpret_cast<const uint32_t*>(p0);
                a[i][1] = *reinterpret_cast<const uint32_t*>(p1);
                a[i][2] = *reinterpret_cast<const uint32_t*>(p0 + 8);
                a[i][3] = *reinterpret_cast<const uint32_t*>(p1 + 8);
            }
            #pragma unroll
            for (int j = 0; j < 8; j++) {
                int nb = wn + j*8 + r;
                const __half* p = &Bs[nb*HPAD + kk + 2*cql];
                b[j][0] = *reinterpret_cast<const uint32_t*>(p);
                b[j][1] = *reinterpret_cast<const uint32_t*>(p + 8);
            }
            #pragma unroll
            for (int i = 0; i < 2; i++)
                #pragma unroll
                for (int j = 0; j < 8; j++)
                    mma_f16(acc[i][j], a[i], b[j]);
        }
        __syncthreads();
    }

    // ---- epilogue: half2 stores ----
    #pragma unroll
    for (int i = 0; i < 2; i++) {
        int row = m0 + wm + i*16 + r;
        #pragma unroll
        for (int j = 0; j < 8; j++) {
            int col = n0 + wn + j*8 + cql*2;
            float v0 = acc[i][j][0], v1 = acc[i][j][1];
            float v2 = acc[i][j][2], v3 = acc[i][j][3];
            if (MODE == 0) {
                float b0 = bias[col], b1 = bias[col+1];
                v0 = fmaxf(v0 + b0, 0.f); v1 = fmaxf(v1 + b1, 0.f);
                v2 = fmaxf(v2 + b0, 0.f); v3 = fmaxf(v3 + b1, 0.f);
                *reinterpret_cast<__half2*>(&C[(size_t)row*HID + col])     = __floats2half2_rn(v0, v1);
                *reinterpret_cast<__half2*>(&C[(size_t)(row+8)*HID + col]) = __floats2half2_rn(v2, v3);
            } else {
                if (col < 64) {
                    *reinterpret_cast<__half2*>(&qo[(size_t)row*ATN + col])     = __floats2half2_rn(v0, v1);
                    *reinterpret_cast<__half2*>(&qo[(size_t)(row+8)*ATN + col]) = __floats2half2_rn(v2, v3);
                } else if (col < 128) {
                    *reinterpret_cast<__half2*>(&kho[(size_t)row*ATN + col - 64])     = __floats2half2_rn(v0, v1);
                    *reinterpret_cast<__half2*>(&kho[(size_t)(row+8)*ATN + col - 64]) = __floats2half2_rn(v2, v3);
                } else {
                    *reinterpret_cast<__half2*>(&vho[(size_t)row*HID + col - 128])     = __floats2half2_rn(v0, v1);
                    *reinterpret_cast<__half2*>(&vho[(size_t)(row+8)*HID + col - 128]) = __floats2half2_rn(v2, v3);
                }
            }
        }
    }
}

// ---------------- sparse graph attention: warp per node ----------------
__global__ void __launch_bounds__(256)
attn_kernel(const __half* __restrict__ q, const __half* __restrict__ kh,
            const __half* __restrict__ vh, __half* __restrict__ hout,
            const float* __restrict__ gcb) {
    const int wid = threadIdx.x >> 5, lane = threadIdx.x & 31;
    const int node = blockIdx.x * 8 + wid;
    __shared__ float qs[8][64];
    __shared__ float ps[8][CAP];

    const int cnt = g_cnt[node];
    if (cnt == 0) {
        #pragma unroll
        for (int e = 0; e < 8; e++) {
            float g = gcb[lane*8 + e];
            hout[(size_t)node*HID + lane*8 + e] = __float2half(1.0f / (1.0f + __expf(-g)));
        }
        return;
    }

    float2 qv = __half22float2(reinterpret_cast<const __half2*>(q + (size_t)node*ATN)[lane]);
    qs[wid][2*lane]   = qv.x;
    qs[wid][2*lane+1] = qv.y;
    __syncwarp();

    const int* nl = g_nbr + (size_t)node * CAP;

    // logits: one neighbor per lane
    for (int t0 = 0; t0 < cnt; t0 += 32) {
        int jn = t0 + lane;
        if (jn < cnt) {
            int j = nl[jn];
            const uint4* kp = reinterpret_cast<const uint4*>(kh + (size_t)j*ATN);
            float d = 0.0f;
            #pragma unroll
            for (int b = 0; b < 8; b++) {
                uint4 kk = kp[b];
                const __half2* hp = reinterpret_cast<const __half2*>(&kk);
                #pragma unroll
                for (int e = 0; e < 4; e++) {
                    float2 f = __half22float2(hp[e]);
                    d = fmaf(qs[wid][b*8 + 2*e],     f.x, d);
                    d = fmaf(qs[wid][b*8 + 2*e + 1], f.y, d);
                }
            }
            ps[wid][jn] = d;
        }
    }
    __syncwarp();

    float mx = -1e30f;
    for (int jn = lane; jn < cnt; jn += 32) mx = fmaxf(mx, ps[wid][jn]);
    #pragma unroll
    for (int o = 16; o; o >>= 1) mx = fmaxf(mx, __shfl_xor_sync(0xffffffffu, mx, o));
    float sum = 0.0f;
    for (int jn = lane; jn < cnt; jn += 32) {
        float e = __expf(ps[wid][jn] - mx);
        ps[wid][jn] = e;
        sum += e;
    }
    #pragma unroll
    for (int o = 16; o; o >>= 1) sum += __shfl_xor_sync(0xffffffffu, sum, o);
    float sinv = 1.0f / sum;
    __syncwarp();

    // V accumulation: lane owns channels [lane*8, lane*8+8)
    float acc[8] = {0,0,0,0,0,0,0,0};
    for (int jn = 0; jn < cnt; jn++) {
        int j = nl[jn];
        float p = ps[wid][jn];
        uint4 vv = reinterpret_cast<const uint4*>(vh + (size_t)j*HID)[lane];
        const __half2* hp = reinterpret_cast<const __half2*>(&vv);
        #pragma unroll
        for (int e = 0; e < 4; e++) {
            float2 f = __half22float2(hp[e]);
            acc[2*e]   = fmaf(p, f.x, acc[2*e]);
            acc[2*e+1] = fmaf(p, f.y, acc[2*e+1]);
        }
    }

    __half2 ov[4];
    #pragma unroll
    for (int e = 0; e < 4; e++) {
        float va = acc[2*e]   * sinv + gcb[lane*8 + 2*e];
        float vb = acc[2*e+1] * sinv + gcb[lane*8 + 2*e + 1];
        ov[e] = __floats2half2_rn(1.0f / (1.0f + __expf(-va)), 1.0f / (1.0f + __expf(-vb)));
    }
    *reinterpret_cast<uint4*>(hout + (size_t)node*HID + lane*8) = *reinterpret_cast<uint4*>(ov);
}

// ---------------- classifier + softmax ----------------
__global__ void __launch_bounds__(256)
classify_kernel(const __half* __restrict__ h, const float* __restrict__ Wc,
                const float* __restrict__ bc, float* __restrict__ out) {
    int node = blockIdx.x * 8 + (threadIdx.x >> 5);
    int lane = threadIdx.x & 31;
    const __half2* hr = reinterpret_cast<const __half2*>(h + (size_t)node * HID);
    float a0 = 0.0f, a1 = 0.0f;
    #pragma unroll
    for (int i = 0; i < 4; i++) {
        int d2 = lane + i*32;           // half2 index, dims 2*d2, 2*d2+1
        float2 f = __half22float2(hr[d2]);
        a0 = fmaf(f.x, Wc[4*d2+0], a0);
        a1 = fmaf(f.x, Wc[4*d2+1], a1);
        a0 = fmaf(f.y, Wc[4*d2+2], a0);
        a1 = fmaf(f.y, Wc[4*d2+3], a1);
    }
    #pragma unroll
    for (int o = 16; o; o >>= 1) {
        a0 += __shfl_xor_sync(0xffffffffu, a0, o);
        a1 += __shfl_xor_sync(0xffffffffu, a1, o);
    }
    if (lane == 0) {
        a0 += bc[0]; a1 += bc[1];
        float m = fmaxf(a0, a1);
        float e0 = __expf(a0 - m), e1 = __expf(a1 - m);
        float inv = 1.0f / (e0 + e1);
        out[node*2 + 0] = e0 * inv;
        out[node*2 + 1] = e1 * inv;
    }
}

// ---------------- launch ----------------
extern "C" void kernel_launch(void* const* d_in, const int* in_sizes, int n_in,
                              void* d_out, int out_size) {
    const int*   x   = (const int*)  d_in[0];
    const int*   cue = (const int*)  d_in[1];
    const float* adj = (const float*)d_in[2];
    const float* emb = (const float*)d_in[3];
    const float* Wh  = (const float*)d_in[4];
    const float* bh  = (const float*)d_in[5];
    const float* Wq  = (const float*)d_in[6];
    const float* Wk  = (const float*)d_in[7];
    const float* Wv  = (const float*)d_in[8];
    const float* gcb = (const float*)d_in[9];
    const float* Wc  = (const float*)d_in[10];
    const float* bc  = (const float*)d_in[11];
    float* out = (float*)d_out;

    void *p_feats, *p_h0, *p_h1, *p_q, *p_kh, *p_vh, *p_WhT, *p_WqkvT;
    cudaGetSymbolAddress(&p_feats, g_feats);
    cudaGetSymbolAddress(&p_h0,    g_h0);
    cudaGetSymbolAddress(&p_h1,    g_h1);
    cudaGetSymbolAddress(&p_q,     g_q);
    cudaGetSymbolAddress(&p_kh,    g_kh);
    cudaGetSymbolAddress(&p_vh,    g_vh);
    cudaGetSymbolAddress(&p_WhT,   g_WhT);
    cudaGetSymbolAddress(&p_WqkvT, g_WqkvT);
    __half* feats = (__half*)p_feats;
    __half* h0    = (__half*)p_h0;
    __half* h1    = (__half*)p_h1;
    __half* qbuf  = (__half*)p_q;
    __half* khb   = (__half*)p_kh;
    __half* vhb   = (__half*)p_vh;
    __half* WhT   = (__half*)p_WhT;
    __half* WqkvT = (__half*)p_WqkvT;

    cudaFuncSetAttribute(gemm_h_kernel<0>, cudaFuncAttributeMaxDynamicSharedMemorySize, SMEM_BYTES);
    cudaFuncSetAttribute(gemm_h_kernel<1>, cudaFuncAttributeMaxDynamicSharedMemorySize, SMEM_BYTES);

    prep_w_kernel<<<QKV, 256>>>(Wh, Wq, Wk, Wv);
    feats_kernel<<<MTOT, 256>>>(x, cue, emb);
    build_nbr_kernel<<<MTOT/8, 256>>>(adj);

    // h0 = relu(feats @ Wh + bh)
    gemm_h_kernel<0><<<dim3(2, 128), 256, SMEM_BYTES>>>(feats, WhT, h0, bh, nullptr, nullptr, nullptr);

    __half* hin = h0;
    __half* hot = h1;
    for (int L = 0; L < 2; L++) {
        gemm_h_kernel<1><<<dim3(3, 128), 256, SMEM_BYTES>>>(hin, WqkvT, nullptr, nullptr, qbuf, khb, vhb);
        attn_kernel<<<MTOT/8, 256>>>(qbuf, khb, vhb, hot, gcb);
        __half* tmp = hin; hin = hot; hot = tmp;
    }

    classify_kernel<<<MTOT/8, 256>>>(hin, Wc, bc, out);
}

// round 6
// speedup vs baseline: 2.7988x; 1.0359x over previous
#include <cuda_runtime.h>
#include <cuda_fp16.h>
#include <cstdint>
#include <math.h>

// ---------------- problem constants ----------------
#define BATCH   8
#define NNODE   2048
#define MTOT    16384
#define HID     256
#define ATN     64
#define EMB     255
#define QKV     384
#define KDIM    256
#define CAP     512
#define HPAD    72

// ---------------- device scratch ----------------
__device__ __align__(16) __half g_feats[MTOT*HID];
__device__ __align__(16) __half g_h0[MTOT*HID];
__device__ __align__(16) __half g_h1[MTOT*HID];
__device__ __align__(16) __half g_q[MTOT*ATN];
__device__ __align__(16) __half g_kh[MTOT*ATN];
__device__ __align__(16) __half g_vh[(size_t)MTOT*HID];
__device__ __align__(16) __half g_WhT[HID*KDIM];
__device__ __align__(16) __half g_WqkvT[QKV*KDIM];
__device__ int   g_nbr[(size_t)MTOT*CAP];
__device__ int   g_cnt[MTOT];

__device__ __forceinline__ uint32_t smem_u32(const void* p) {
    uint32_t a;
    asm("{ .reg .u64 t; cvta.to.shared.u64 t, %1; cvt.u32.u64 %0, t; }" : "=r"(a) : "l"(p));
    return a;
}
__device__ __forceinline__ void cp16(uint32_t dst, const void* src) {
    asm volatile("cp.async.cg.shared.global [%0], [%1], 16;" :: "r"(dst), "l"(src) : "memory");
}
__device__ __forceinline__ void ldm_x4(uint32_t* r, uint32_t addr) {
    asm volatile("ldmatrix.sync.aligned.m8n8.x4.shared.b16 {%0,%1,%2,%3}, [%4];"
        : "=r"(r[0]), "=r"(r[1]), "=r"(r[2]), "=r"(r[3]) : "r"(addr));
}
__device__ __forceinline__ void mma_f16(float* c, const uint32_t* a, const uint32_t* b) {
    asm volatile(
        "mma.sync.aligned.m16n8k16.row.col.f32.f16.f16.f32 "
        "{%0,%1,%2,%3}, {%4,%5,%6,%7}, {%8,%9}, {%0,%1,%2,%3};"
        : "+f"(c[0]), "+f"(c[1]), "+f"(c[2]), "+f"(c[3])
        : "r"(a[0]), "r"(a[1]), "r"(a[2]), "r"(a[3]), "r"(b[0]), "r"(b[1]));
}

// ---------------- fused prep: build_nbr + feats + weight transpose ----------
// grid: [0,2048) nbr (8 rows each) | [2048,10240) feats (2 nodes each) | [10240,10624) prep_w
#define NB_NBR   2048
#define NB_FEATS 8192
#define NB_W     384

__global__ void __launch_bounds__(256)
prep_kernel(const float* __restrict__ adj,
            const int* __restrict__ x, const int* __restrict__ cue,
            const float* __restrict__ emb,
            const float* __restrict__ Wh, const float* __restrict__ Wq,
            const float* __restrict__ Wk, const float* __restrict__ Wv) {
    int bid = blockIdx.x;
    int t = threadIdx.x;
    if (bid < NB_NBR) {
        int row  = bid * 8 + (t >> 5);
        int lane = t & 31;
        const float4* ar = reinterpret_cast<const float4*>(adj + (size_t)row * NNODE);
        int* dst = g_nbr + (size_t)row * CAP;
        int base = 0;
        for (int j0 = 0; j0 < NNODE; j0 += 128) {
            float4 v = ar[(j0 >> 2) + lane];
            int h0 = v.x > 0.f, h1 = v.y > 0.f, h2 = v.z > 0.f, h3 = v.w > 0.f;
            int c4 = h0 + h1 + h2 + h3;
            int sc = c4;
            #pragma unroll
            for (int o = 1; o < 32; o <<= 1) {
                int nx = __shfl_up_sync(0xffffffffu, sc, o);
                if (lane >= o) sc += nx;
            }
            int pos = base + sc - c4;
            int jb = j0 + lane*4;
            if (h0) { if (pos < CAP) dst[pos] = jb;   pos++; }
            if (h1) { if (pos < CAP) dst[pos] = jb+1; pos++; }
            if (h2) { if (pos < CAP) dst[pos] = jb+2; pos++; }
            if (h3) { if (pos < CAP) dst[pos] = jb+3; pos++; }
            base += __shfl_sync(0xffffffffu, sc, 31);
        }
        if (lane == 0) g_cnt[row] = min(base, CAP);
    } else if (bid < NB_NBR + NB_FEATS) {
        int m = (bid - NB_NBR) * 2 + (t >> 7);
        int d0 = (t & 127) * 2;
        int xi = x[m];
        float cuev = (float)cue[m];
        const float* er = emb + (size_t)xi * EMB;
        float v0 = (d0     < EMB) ? er[d0]   : cuev;
        float v1 = (d0 + 1 < EMB) ? er[d0+1] : cuev;
        *reinterpret_cast<__half2*>(&g_feats[(size_t)m*HID + d0]) = __floats2half2_rn(v0, v1);
    } else {
        int idx = (bid - NB_NBR - NB_FEATS) * 256 + t;
        int n = idx >> 8, k = idx & 255;
        if (idx < 256*256)
            g_WhT[n*256 + k] = __float2half(Wh[k*256 + n]);
        float v = (n < 64) ? Wq[k*64 + n] : (n < 128) ? Wk[k*64 + (n-64)] : Wv[k*256 + (n-128)];
        g_WqkvT[n*256 + k] = __float2half(v);
    }
}

// ---------------- fp16 GEMM, ldmatrix + cp.async 2-stage, tile 128x128xBK64 --
#define TILE_HALVES (128*HPAD)
#define STAGE_HALVES (2*TILE_HALVES)
#define SMEM_BYTES  (2*STAGE_HALVES*2)

template<int MODE>
__global__ void __launch_bounds__(256, 2)
gemm_h_kernel(const __half* __restrict__ A, const __half* __restrict__ BT,
              __half* __restrict__ C, const float* __restrict__ bias,
              __half* __restrict__ qo, __half* __restrict__ kho, __half* __restrict__ vho) {
    extern __shared__ __half sm[];
    const int tid = threadIdx.x;
    const int lane = tid & 31, wid = tid >> 5;
    const int wm = (wid & 3) * 32;
    const int wn = (wid >> 2) * 64;
    const int m0 = blockIdx.y * 128;
    const int n0 = blockIdx.x * 128;
    const int r = lane >> 2, cql = lane & 3;
    const uint32_t sbase = smem_u32(sm);

    // ldmatrix per-lane base offsets (in halves)
    const uint32_t aBase = (uint32_t)((wm + (lane & 15)) * HPAD + ((lane >> 4) << 3));
    const uint32_t bBase = (uint32_t)((wn + (lane & 7) + ((lane >> 4) << 3)) * HPAD
                                      + (((lane >> 3) & 1) << 3));

    float acc[2][8][4];
    #pragma unroll
    for (int i = 0; i < 2; i++)
        #pragma unroll
        for (int j = 0; j < 8; j++)
            #pragma unroll
            for (int e = 0; e < 4; e++) acc[i][j][e] = 0.0f;

    auto stage = [&](int buf, int kt) {
        uint32_t dbase = sbase + (uint32_t)(buf * STAGE_HALVES) * 2u;
        #pragma unroll
        for (int i = 0; i < 4; i++) {
            int idx = tid + i*256;
            int row = idx >> 3, ck = (idx & 7) << 3;
            cp16(dbase + (uint32_t)(row*HPAD + ck)*2u,
                 A + (size_t)(m0+row)*KDIM + kt + ck);
        }
        #pragma unroll
        for (int i = 0; i < 4; i++) {
            int idx = tid + i*256;
            int row = idx >> 3, ck = (idx & 7) << 3;
            cp16(dbase + (uint32_t)(TILE_HALVES + row*HPAD + ck)*2u,
                 BT + (size_t)(n0+row)*KDIM + kt + ck);
        }
        asm volatile("cp.async.commit_group;" ::: "memory");
    };

    stage(0, 0);
    for (int c = 0; c < 4; c++) {
        asm volatile("cp.async.wait_group 0;" ::: "memory");
        __syncthreads();
        if (c < 3) stage((c+1) & 1, (c+1)*64);

        const uint32_t As = sbase + (uint32_t)((c & 1) * STAGE_HALVES) * 2u;
        const uint32_t Bs = As + (uint32_t)TILE_HALVES * 2u;

        #pragma unroll
        for (int k16 = 0; k16 < 4; k16++) {
            const uint32_t kk = k16 * 16;
            uint32_t a[2][4], b[8][2];
            #pragma unroll
            for (int i = 0; i < 2; i++)
                ldm_x4(a[i], As + (aBase + (uint32_t)(i*16*HPAD) + kk) * 2u);
            #pragma unroll
            for (int p = 0; p < 4; p++) {
                uint32_t rb[4];
                ldm_x4(rb, Bs + (bBase + (uint32_t)(p*16*HPAD) + kk) * 2u);
                b[2*p][0]   = rb[0]; b[2*p][1]   = rb[1];
                b[2*p+1][0] = rb[2]; b[2*p+1][1] = rb[3];
            }
            #pragma unroll
            for (int i = 0; i < 2; i++)
                #pragma unroll
                for (int j = 0; j < 8; j++)
                    mma_f16(acc[i][j], a[i], b[j]);
        }
        __syncthreads();
    }

    #pragma unroll
    for (int i = 0; i < 2; i++) {
        int row = m0 + wm + i*16 + r;
        #pragma unroll
        for (int j = 0; j < 8; j++) {
            int col = n0 + wn + j*8 + cql*2;
            float v0 = acc[i][j][0], v1 = acc[i][j][1];
            float v2 = acc[i][j][2], v3 = acc[i][j][3];
            if (MODE == 0) {
                float b0 = bias[col], b1 = bias[col+1];
                v0 = fmaxf(v0 + b0, 0.f); v1 = fmaxf(v1 + b1, 0.f);
                v2 = fmaxf(v2 + b0, 0.f); v3 = fmaxf(v3 + b1, 0.f);
                *reinterpret_cast<__half2*>(&C[(size_t)row*HID + col])     = __floats2half2_rn(v0, v1);
                *reinterpret_cast<__half2*>(&C[(size_t)(row+8)*HID + col]) = __floats2half2_rn(v2, v3);
            } else {
                if (col < 64) {
                    *reinterpret_cast<__half2*>(&qo[(size_t)row*ATN + col])     = __floats2half2_rn(v0, v1);
                    *reinterpret_cast<__half2*>(&qo[(size_t)(row+8)*ATN + col]) = __floats2half2_rn(v2, v3);
                } else if (col < 128) {
                    *reinterpret_cast<__half2*>(&kho[(size_t)row*ATN + col - 64])     = __floats2half2_rn(v0, v1);
                    *reinterpret_cast<__half2*>(&kho[(size_t)(row+8)*ATN + col - 64]) = __floats2half2_rn(v2, v3);
                } else {
                    *reinterpret_cast<__half2*>(&vho[(size_t)row*HID + col - 128])     = __floats2half2_rn(v0, v1);
                    *reinterpret_cast<__half2*>(&vho[(size_t)(row+8)*HID + col - 128]) = __floats2half2_rn(v2, v3);
                }
            }
        }
    }
}

// ---------------- sparse graph attention: warp per node ----------------
__global__ void __launch_bounds__(256)
attn_kernel(const __half* __restrict__ q, const __half* __restrict__ kh,
            const __half* __restrict__ vh, __half* __restrict__ hout,
            const float* __restrict__ gcb) {
    const int wid = threadIdx.x >> 5, lane = threadIdx.x & 31;
    const int node = blockIdx.x * 8 + wid;
    __shared__ float qs[8][64];
    __shared__ float ps[8][CAP];
    __shared__ int   js[8][CAP];

    const int cnt = g_cnt[node];
    if (cnt == 0) {
        #pragma unroll
        for (int e = 0; e < 8; e++) {
            float g = gcb[lane*8 + e];
            hout[(size_t)node*HID + lane*8 + e] = __float2half(1.0f / (1.0f + __expf(-g)));
        }
        return;
    }

    float2 qv = __half22float2(reinterpret_cast<const __half2*>(q + (size_t)node*ATN)[lane]);
    qs[wid][2*lane]   = qv.x;
    qs[wid][2*lane+1] = qv.y;
    __syncwarp();

    const int* nl = g_nbr + (size_t)node * CAP;

    for (int t0 = 0; t0 < cnt; t0 += 32) {
        int jn = t0 + lane;
        if (jn < cnt) {
            int j = nl[jn];
            js[wid][jn] = j;
            const uint4* kp = reinterpret_cast<const uint4*>(kh + (size_t)j*ATN);
            float d = 0.0f;
            #pragma unroll
            for (int b = 0; b < 8; b++) {
                uint4 kk = kp[b];
                const __half2* hp = reinterpret_cast<const __half2*>(&kk);
                #pragma unroll
                for (int e = 0; e < 4; e++) {
                    float2 f = __half22float2(hp[e]);
                    d = fmaf(qs[wid][b*8 + 2*e],     f.x, d);
                    d = fmaf(qs[wid][b*8 + 2*e + 1], f.y, d);
                }
            }
            ps[wid][jn] = d;
        }
    }
    __syncwarp();

    float mx = -1e30f;
    for (int jn = lane; jn < cnt; jn += 32) mx = fmaxf(mx, ps[wid][jn]);
    #pragma unroll
    for (int o = 16; o; o >>= 1) mx = fmaxf(mx, __shfl_xor_sync(0xffffffffu, mx, o));
    float sum = 0.0f;
    for (int jn = lane; jn < cnt; jn += 32) {
        float e = __expf(ps[wid][jn] - mx);
        ps[wid][jn] = e;
        sum += e;
    }
    #pragma unroll
    for (int o = 16; o; o >>= 1) sum += __shfl_xor_sync(0xffffffffu, sum, o);
    float sinv = 1.0f / sum;
    __syncwarp();

    // V accumulation with prefetch depth 2; lane owns channels [lane*8, lane*8+8)
    float acc[8] = {0,0,0,0,0,0,0,0};
    uint4 v0, v1;
    v1 = make_uint4(0,0,0,0);
    v0 = reinterpret_cast<const uint4*>(vh + (size_t)js[wid][0]*HID)[lane];
    if (cnt > 1)
        v1 = reinterpret_cast<const uint4*>(vh + (size_t)js[wid][1]*HID)[lane];
    for (int jn = 0; jn < cnt; jn++) {
        uint4 cur = v0;
        v0 = v1;
        if (jn + 2 < cnt)
            v1 = reinterpret_cast<const uint4*>(vh + (size_t)js[wid][jn+2]*HID)[lane];
        float p = ps[wid][jn];
        const __half2* hp = reinterpret_cast<const __half2*>(&cur);
        #pragma unroll
        for (int e = 0; e < 4; e++) {
            float2 f = __half22float2(hp[e]);
            acc[2*e]   = fmaf(p, f.x, acc[2*e]);
            acc[2*e+1] = fmaf(p, f.y, acc[2*e+1]);
        }
    }

    __half2 ov[4];
    #pragma unroll
    for (int e = 0; e < 4; e++) {
        float va = acc[2*e]   * sinv + gcb[lane*8 + 2*e];
        float vb = acc[2*e+1] * sinv + gcb[lane*8 + 2*e + 1];
        ov[e] = __floats2half2_rn(1.0f / (1.0f + __expf(-va)), 1.0f / (1.0f + __expf(-vb)));
    }
    *reinterpret_cast<uint4*>(hout + (size_t)node*HID + lane*8) = *reinterpret_cast<uint4*>(ov);
}

// ---------------- classifier + softmax ----------------
__global__ void __launch_bounds__(256)
classify_kernel(const __half* __restrict__ h, const float* __restrict__ Wc,
                const float* __restrict__ bc, float* __restrict__ out) {
    int node = blockIdx.x * 8 + (threadIdx.x >> 5);
    int lane = threadIdx.x & 31;
    const __half2* hr = reinterpret_cast<const __half2*>(h + (size_t)node * HID);
    float a0 = 0.0f, a1 = 0.0f;
    #pragma unroll
    for (int i = 0; i < 4; i++) {
        int d2 = lane + i*32;
        float2 f = __half22float2(hr[d2]);
        a0 = fmaf(f.x, Wc[4*d2+0], a0);
        a1 = fmaf(f.x, Wc[4*d2+1], a1);
        a0 = fmaf(f.y, Wc[4*d2+2], a0);
        a1 = fmaf(f.y, Wc[4*d2+3], a1);
    }
    #pragma unroll
    for (int o = 16; o; o >>= 1) {
        a0 += __shfl_xor_sync(0xffffffffu, a0, o);
        a1 += __shfl_xor_sync(0xffffffffu, a1, o);
    }
    if (lane == 0) {
        a0 += bc[0]; a1 += bc[1];
        float m = fmaxf(a0, a1);
        float e0 = __expf(a0 - m), e1 = __expf(a1 - m);
        float inv = 1.0f / (e0 + e1);
        out[node*2 + 0] = e0 * inv;
        out[node*2 + 1] = e1 * inv;
    }
}

// ---------------- launch ----------------
extern "C" void kernel_launch(void* const* d_in, const int* in_sizes, int n_in,
                              void* d_out, int out_size) {
    const int*   x   = (const int*)  d_in[0];
    const int*   cue = (const int*)  d_in[1];
    const float* adj = (const float*)d_in[2];
    const float* emb = (const float*)d_in[3];
    const float* Wh  = (const float*)d_in[4];
    const float* bh  = (const float*)d_in[5];
    const float* Wq  = (const float*)d_in[6];
    const float* Wk  = (const float*)d_in[7];
    const float* Wv  = (const float*)d_in[8];
    const float* gcb = (const float*)d_in[9];
    const float* Wc  = (const float*)d_in[10];
    const float* bc  = (const float*)d_in[11];
    float* out = (float*)d_out;

    void *p_feats, *p_h0, *p_h1, *p_q, *p_kh, *p_vh, *p_WhT, *p_WqkvT;
    cudaGetSymbolAddress(&p_feats, g_feats);
    cudaGetSymbolAddress(&p_h0,    g_h0);
    cudaGetSymbolAddress(&p_h1,    g_h1);
    cudaGetSymbolAddress(&p_q,     g_q);
    cudaGetSymbolAddress(&p_kh,    g_kh);
    cudaGetSymbolAddress(&p_vh,    g_vh);
    cudaGetSymbolAddress(&p_WhT,   g_WhT);
    cudaGetSymbolAddress(&p_WqkvT, g_WqkvT);
    __half* feats = (__half*)p_feats;
    __half* h0    = (__half*)p_h0;
    __half* h1    = (__half*)p_h1;
    __half* qbuf  = (__half*)p_q;
    __half* khb   = (__half*)p_kh;
    __half* vhb   = (__half*)p_vh;
    __half* WhT   = (__half*)p_WhT;
    __half* WqkvT = (__half*)p_WqkvT;

    cudaFuncSetAttribute(gemm_h_kernel<0>, cudaFuncAttributeMaxDynamicSharedMemorySize, SMEM_BYTES);
    cudaFuncSetAttribute(gemm_h_kernel<1>, cudaFuncAttributeMaxDynamicSharedMemorySize, SMEM_BYTES);

    prep_kernel<<<NB_NBR + NB_FEATS + NB_W, 256>>>(adj, x, cue, emb, Wh, Wq, Wk, Wv);

    gemm_h_kernel<0><<<dim3(2, 128), 256, SMEM_BYTES>>>(feats, WhT, h0, bh, nullptr, nullptr, nullptr);

    __half* hin = h0;
    __half* hot = h1;
    for (int L = 0; L < 2; L++) {
        gemm_h_kernel<1><<<dim3(3, 128), 256, SMEM_BYTES>>>(hin, WqkvT, nullptr, nullptr, qbuf, khb, vhb);
        attn_kernel<<<MTOT/8, 256>>>(qbuf, khb, vhb, hot, gcb);
        __half* tmp = hin; hin = hot; hot = tmp;
    }

    classify_kernel<<<MTOT/8, 256>>>(hin, Wc, bc, out);
}